// round 12
// baseline (speedup 1.0000x reference)
#include <cuda_runtime.h>
#include <cstdint>

#define B_TOTAL 65536
#define HDIM    256
#define GATE3   768

// ping-pong hidden-state buffers (allocation-free scratch)
__device__ float g_h[2ULL * B_TOTAL * HDIM];

#define A_STRIDE 132   // 128x128 A half-tile; 132 mod 32 = 4 -> bank map 4*grp+tg, conflict-free
#define W_STRIDE 72    // weight tile [16 k][32 j] padded stride (bank map 8*tg+n, conflict-free)
#define SMEM_WORDS (128 * A_STRIDE + 3 * 2 * 16 * W_STRIDE)
#define SMEM_BYTES (SMEM_WORDS * 4)   // 95232 B -> 2 CTAs/SM (190464 < 228KB)

__device__ __forceinline__ unsigned f2tf(float f) {
    unsigned u;
    asm("cvt.rna.tf32.f32 %0, %1;" : "=r"(u) : "f"(f));
    return u;
}

__device__ __forceinline__ void mma_tf32(float c[4],
                                         unsigned a0, unsigned a1, unsigned a2, unsigned a3,
                                         unsigned b0, unsigned b1) {
    asm volatile(
        "mma.sync.aligned.m16n8k8.row.col.f32.tf32.tf32.f32 "
        "{%0,%1,%2,%3}, {%4,%5,%6,%7}, {%8,%9}, {%0,%1,%2,%3};\n"
        : "+f"(c[0]), "+f"(c[1]), "+f"(c[2]), "+f"(c[3])
        : "r"(a0), "r"(a1), "r"(a2), "r"(a3), "r"(b0), "r"(b1));
}

// One GRU cell, fully fused.  Grid: (8 j-chunks of 32, 512 batch tiles of 128).
// CTA = 256 threads = 8 warps in a 4(M) x 2(N) grid; warp tile 32m x 16n.
// Per-work fragment wavefronts IDENTICAL to R8 (160/k8 per 128x32 output),
// but A staged in k128 halves -> smem 93KB -> 2 CTAs/SM, which R11 proved
// lifts L1 utilization 65% -> ~81% by hiding barrier/staging gaps.
__global__ void __launch_bounds__(256, 2)
gru_unit(const float* __restrict__ x, const float* __restrict__ hprev,
         float* __restrict__ hout,
         const float* __restrict__ Wih, const float* __restrict__ Whh,
         const float* __restrict__ bih, const float* __restrict__ bhh) {
    extern __shared__ unsigned smem[];
    unsigned* As = smem;                       // [128][A_STRIDE] (tf32 bits, k128 half)
    unsigned* Ws = smem + 128 * A_STRIDE;      // [3 acc][2 buf][16 k][W_STRIDE]

    const int tid  = threadIdx.x;
    const int lane = tid & 31;
    const int wid  = tid >> 5;
    const int grp  = lane >> 2;    // 0..7
    const int tg   = lane & 3;     // 0..3
    const int wm   = wid >> 1;     // 0..3  (rows 32*wm)
    const int wn   = wid & 1;      // 0..1  (cols 16*wn)
    const int j0   = blockIdx.x * 32;
    const int b0   = blockIdx.y * 128;

    float C[4][2][2][4];           // [r,z,n_i,n_h][m-tile][n-tile][cfrag]
#pragma unroll
    for (int a = 0; a < 4; a++)
#pragma unroll
        for (int mt = 0; mt < 2; mt++)
#pragma unroll
            for (int t = 0; t < 2; t++)
#pragma unroll
                for (int c = 0; c < 4; c++) C[a][mt][t][c] = 0.f;

    for (int phase = 0; phase < 2; phase++) {
        const float* Asrc = phase ? hprev : x;
        const float* Wsrc = phase ? Whh : Wih;

        for (int kh = 0; kh < 2; kh++) {
            __syncthreads();   // all readers of As / Ws from previous segment done

            // ---- stage A half-tile: 128 rows x 128 k, rna-rounded to tf32 ----
            {
                const float4* src4 = reinterpret_cast<const float4*>(Asrc + (size_t)b0 * 256);
#pragma unroll
                for (int i = 0; i < 16; i++) {
                    int idx = tid + i * 256;       // 0..4095
                    int row = idx >> 5;
                    int q   = idx & 31;
                    float4 v = src4[row * 64 + kh * 32 + q];
                    uint4 u;
                    u.x = f2tf(v.x); u.y = f2tf(v.y); u.z = f2tf(v.z); u.w = f2tf(v.w);
                    *reinterpret_cast<uint4*>(&As[row * A_STRIDE + 4 * q]) = u;
                }
            }

            // ---- weight tile LDG helper (3 gates x [32 j][16 k], float4/thread) ----
            uint4 wcur[2], wnxt[2];
            auto ldgW = [&](int s, uint4 wr[2]) {
#pragma unroll
                for (int i = 0; i < 2; i++) {
                    int idx = tid + i * 256;        // 0..511; 384 active
                    if (idx < 384) {
                        int a   = idx >> 7;         // gate 0..2
                        int rq  = idx & 127;
                        int r32 = rq >> 2;          // j within chunk 0..31
                        int q   = rq & 3;           // k quad
                        const float* gp = Wsrc + (size_t)(a * 256 + j0 + r32) * 256
                                        + kh * 128 + s * 16 + q * 4;
                        float4 v = *reinterpret_cast<const float4*>(gp);
                        wr[i].x = f2tf(v.x); wr[i].y = f2tf(v.y);
                        wr[i].z = f2tf(v.z); wr[i].w = f2tf(v.w);
                    }
                }
            };
            auto stsW = [&](int buf, uint4 wr[2]) {
#pragma unroll
                for (int i = 0; i < 2; i++) {
                    int idx = tid + i * 256;
                    if (idx < 384) {
                        int a   = idx >> 7;
                        int rq  = idx & 127;
                        int r32 = rq >> 2;
                        int q   = rq & 3;
                        unsigned* wb = Ws + (size_t)((a * 2 + buf) * 16) * W_STRIDE;
                        wb[(q * 4 + 0) * W_STRIDE + r32] = wr[i].x;
                        wb[(q * 4 + 1) * W_STRIDE + r32] = wr[i].y;
                        wb[(q * 4 + 2) * W_STRIDE + r32] = wr[i].z;
                        wb[(q * 4 + 3) * W_STRIDE + r32] = wr[i].w;
                    }
                }
            };

            ldgW(0, wcur);
            __syncthreads();   // A half visible (buf0 writers also gated)
            stsW(0, wcur);
            __syncthreads();   // weight buf 0 visible

            const int rowa0 = 32 * wm + grp;       // m-tile 0, low row
            for (int s = 0; s < 8; s++) {
                if (s < 7) ldgW(s + 1, wnxt);
#pragma unroll
                for (int gsub = 0; gsub < 2; gsub++) {
                    const int kc = s * 16 + gsub * 8 + tg;   // 0..127 within half
                    // A fragments for both m-tiles (scalar LDS, conflict-free)
                    unsigned a0[2], a1[2], a2[2], a3[2];
#pragma unroll
                    for (int mt = 0; mt < 2; mt++) {
                        int r0 = rowa0 + 16 * mt;
                        a0[mt] = As[r0       * A_STRIDE + kc];
                        a1[mt] = As[(r0 + 8) * A_STRIDE + kc];
                        a2[mt] = As[r0       * A_STRIDE + kc + 4];
                        a3[mt] = As[(r0 + 8) * A_STRIDE + kc + 4];
                    }
#pragma unroll
                    for (int acc = 0; acc < 3; acc++) {
                        const int ai = (acc == 2) ? (2 + phase) : acc;
                        const unsigned* wb =
                            Ws + (size_t)((acc * 2 + (s & 1)) * 16 + gsub * 8) * W_STRIDE;
#pragma unroll
                        for (int t = 0; t < 2; t++) {
                            int n = wn * 16 + t * 8 + grp;
                            unsigned bb0 = wb[tg * W_STRIDE + n];
                            unsigned bb1 = wb[(tg + 4) * W_STRIDE + n];
#pragma unroll
                            for (int mt = 0; mt < 2; mt++)
                                mma_tf32(C[ai][mt][t],
                                         a0[mt], a1[mt], a2[mt], a3[mt], bb0, bb1);
                        }
                    }
                }
                // Single barrier per step: stsW targets buffer (s+1)&1 whose last
                // readers were fenced by the previous iteration's barrier.
                if (s < 7) stsW((s + 1) & 1, wnxt);
                __syncthreads();
            }
        }
    }

    // ---- fused gate epilogue (exact fp32 h_prev) ----
#pragma unroll
    for (int t = 0; t < 2; t++) {
        int col0 = j0 + wn * 16 + t * 8 + 2 * tg;
#pragma unroll
        for (int cc = 0; cc < 2; cc++) {
            int j = col0 + cc;
            float br  = bih[j]       + bhh[j];
            float bz  = bih[256 + j] + bhh[256 + j];
            float bni = bih[512 + j];
            float bnh = bhh[512 + j];
#pragma unroll
            for (int mt = 0; mt < 2; mt++) {
                int mrow = b0 + 32 * wm + 16 * mt + grp;
#pragma unroll
                for (int rr = 0; rr < 2; rr++) {
                    int row = mrow + rr * 8;
                    int ci  = rr * 2 + cc;
                    float vr = C[0][mt][t][ci] + br;
                    float vz = C[1][mt][t][ci] + bz;
                    float n1 = C[2][mt][t][ci] + bni;
                    float n2 = C[3][mt][t][ci] + bnh;
                    float r  = 1.f / (1.f + __expf(-vr));
                    float z  = 1.f / (1.f + __expf(-vz));
                    float n  = tanhf(n1 + r * n2);
                    float hp = hprev[(size_t)row * 256 + j];
                    hout[(size_t)row * 256 + j] = (1.f - z) * n + z * hp;
                }
            }
        }
    }
}

__global__ void init_h(const float* __restrict__ h0, float* __restrict__ dst) {
    size_t total = (size_t)B_TOTAL * HDIM;
    for (size_t k = blockIdx.x * (size_t)blockDim.x + threadIdx.x; k < total;
         k += (size_t)gridDim.x * blockDim.x)
        dst[k] = h0[k & 255];
}

extern "C" void kernel_launch(void* const* d_in, const int* in_sizes, int n_in,
                              void* d_out, int out_size) {
    const float* x   = (const float*)d_in[0];
    const float* Wih = (const float*)d_in[1];
    const float* Whh = (const float*)d_in[2];
    const float* bih = (const float*)d_in[3];
    const float* bhh = (const float*)d_in[4];
    const float* h0  = (const float*)d_in[5];
    float* out = (float*)d_out;

    float* hb = nullptr;
    cudaGetSymbolAddress((void**)&hb, g_h);
    float* hbuf0 = hb;
    float* hbuf1 = hb + (size_t)B_TOTAL * HDIM;

    cudaFuncSetAttribute(gru_unit, cudaFuncAttributeMaxDynamicSharedMemorySize, SMEM_BYTES);

    init_h<<<512, 256>>>(h0, hbuf0);

    for (int u = 0; u < 8; u++) {
        const float* src = (u & 1) ? hbuf1 : hbuf0;
        float*       dst = (u == 7) ? out : ((u & 1) ? hbuf0 : hbuf1);
        gru_unit<<<dim3(8, 512), 256, SMEM_BYTES>>>(
            x, src, dst,
            Wih + (size_t)u * GATE3 * 256,
            Whh + (size_t)u * GATE3 * 256,
            bih + (size_t)u * GATE3,
            bhh + (size_t)u * GATE3);
    }
}

// round 14
// speedup vs baseline: 2.5782x; 2.5782x over previous
#include <cuda_runtime.h>
#include <cstdint>

#define B_TOTAL 65536
#define HDIM    256

// ---------------- scratch (allocation-free) ----------------
__device__ float    g_h [2ULL * B_TOTAL * HDIM];   // exact fp32 hidden (ping-pong)
__device__ unsigned g_ht[2ULL * B_TOTAL * HDIM];   // tf32-bit hidden (ping-pong)
__device__ unsigned g_xt[(size_t)B_TOTAL * HDIM];  // tf32-bit x
// weights pre-converted + pre-tiled: [u][ph][jc4][s16][row48 = gate*16+k][64 j]
#define WT_PER_UNIT (2 * 4 * 16 * 48 * 64)
__device__ unsigned g_wt[8ULL * WT_PER_UNIT];

#define A_STRIDE 260                 // bank map 4*grp+tg, conflict-free (proven R5/R8)
#define A_WORDS  (128 * A_STRIDE)
#define W_STRIDE 72                  // bank map 8*tg+grp, conflict-free
#define WSTG     (48 * W_STRIDE)     // 3456 words per W ring stage
#define SMEM_WORDS (A_WORDS + 3 * WSTG)
#define SMEM_BYTES (SMEM_WORDS * 4)  // 174592 B (occ 1 by design; RF caps it anyway)

__device__ __forceinline__ unsigned f2tf(float f) {
    unsigned u;
    asm("cvt.rna.tf32.f32 %0, %1;" : "=r"(u) : "f"(f));
    return u;
}
__device__ __forceinline__ uint32_t smem_u32(const void* p) {
    uint32_t a;
    asm("{ .reg .u64 t; cvta.to.shared.u64 t, %1; cvt.u32.u64 %0, t; }"
        : "=r"(a) : "l"(p));
    return a;
}
#define CP16(dst_u32, src_ptr) \
    asm volatile("cp.async.cg.shared.global [%0], [%1], 16;" \
                 :: "r"(dst_u32), "l"(src_ptr))
#define CP_COMMIT()  asm volatile("cp.async.commit_group;" ::: "memory")
#define CP_WAIT1()   asm volatile("cp.async.wait_group 1;" ::: "memory")
#define CP_WAIT0()   asm volatile("cp.async.wait_group 0;" ::: "memory")

__device__ __forceinline__ void mma_tf32(float c[4],
                                         unsigned a0, unsigned a1, unsigned a2, unsigned a3,
                                         unsigned b0, unsigned b1) {
    asm volatile(
        "mma.sync.aligned.m16n8k8.row.col.f32.tf32.tf32.f32 "
        "{%0,%1,%2,%3}, {%4,%5,%6,%7}, {%8,%9}, {%0,%1,%2,%3};\n"
        : "+f"(c[0]), "+f"(c[1]), "+f"(c[2]), "+f"(c[3])
        : "r"(a0), "r"(a1), "r"(a2), "r"(a3), "r"(b0), "r"(b1));
}

// One GRU cell.  Grid (4 j-chunks of 64, 512 batch tiles of 128), 512 threads,
// 16 warps 4(M)x4(N), warp tile 32m x 16n (R8 economics, best measured).
// All mainloop staging is cp.async from PRE-CONVERTED tf32-bit scratch:
// no f2tf, no LDG->RF->STS round trip, 3-stage W ring issued 2 steps ahead.
__global__ void __launch_bounds__(512)
gru_unit(const unsigned* __restrict__ xt, const float* __restrict__ hprev,
         const unsigned* __restrict__ htprev,
         float* __restrict__ hout, unsigned* __restrict__ htout,
         const unsigned* __restrict__ wt,           // this unit's g_wt slice
         const float* __restrict__ bih, const float* __restrict__ bhh) {
    extern __shared__ unsigned smem[];
    const uint32_t sbase = smem_u32(smem);
    unsigned* As = smem;                     // [128][A_STRIDE]
    unsigned* Ws = smem + A_WORDS;           // 3-stage ring [48][W_STRIDE]

    const int tid  = threadIdx.x;
    const int lane = tid & 31;
    const int wid  = tid >> 5;
    const int grp  = lane >> 2;
    const int tg   = lane & 3;
    const int wm   = wid & 3;                // rows 32*wm
    const int wn   = wid >> 2;               // cols 16*wn
    const int jc   = blockIdx.x;
    const int j0   = jc * 64;
    const int b0   = blockIdx.y * 128;

    float C[4][2][2][4];
#pragma unroll
    for (int a = 0; a < 4; a++)
#pragma unroll
        for (int mt = 0; mt < 2; mt++)
#pragma unroll
            for (int t = 0; t < 2; t++)
#pragma unroll
                for (int c = 0; c < 4; c++) C[a][mt][t][c] = 0.f;

    for (int phase = 0; phase < 2; phase++) {
        const unsigned* asrc = (phase ? htprev : xt) + (size_t)b0 * 256;
        const unsigned* wbase = wt + (size_t)(phase * 4 + jc) * 16 * 48 * 64;

        __syncthreads();   // previous phase/epilogue consumers done with smem

        // ---- issue A tile copy (group 0): 128 rows x 64 16B-granules ----
#pragma unroll
        for (int i = 0; i < 16; i++) {
            int g = tid + i * 512;           // 0..8191
            int row = g >> 6, q = g & 63;
            CP16(sbase + (uint32_t)(row * A_STRIDE + q * 4) * 4,
                 asrc + (size_t)row * 256 + q * 4);
        }
        CP_COMMIT();

        auto issueW = [&](int s, int stage) {
#pragma unroll
            for (int i = 0; i < 2; i++) {
                int g = tid + i * 512;       // 768 granules: 48 rows x 16
                if (g < 768) {
                    int row = g >> 4, q = g & 15;
                    CP16(sbase + (uint32_t)(A_WORDS + stage * WSTG + row * W_STRIDE + q * 4) * 4,
                         wbase + (size_t)s * 3072 + row * 64 + q * 4);
                }
            }
            CP_COMMIT();
        };

        issueW(0, 0);
        issueW(1, 1);
        CP_WAIT1();          // A + W0 landed (W1 may still fly)
        __syncthreads();

        const int rowa0 = 32 * wm + grp;
        for (int s = 0; s < 16; s++) {
            if (s < 14) issueW(s + 2, (s + 2) % 3);
            const unsigned* wstage = Ws + (size_t)(s % 3) * WSTG;
#pragma unroll
            for (int gsub = 0; gsub < 2; gsub++) {
                const int kc = s * 16 + gsub * 8 + tg;
                unsigned a0[2], a1[2], a2[2], a3[2];
#pragma unroll
                for (int mt = 0; mt < 2; mt++) {
                    int r0 = rowa0 + 16 * mt;
                    a0[mt] = As[r0       * A_STRIDE + kc];
                    a1[mt] = As[(r0 + 8) * A_STRIDE + kc];
                    a2[mt] = As[r0       * A_STRIDE + kc + 4];
                    a3[mt] = As[(r0 + 8) * A_STRIDE + kc + 4];
                }
#pragma unroll
                for (int gate = 0; gate < 3; gate++) {
                    const int ai = (gate == 2) ? (2 + phase) : gate;
                    const unsigned* wb = wstage + gate * (16 * W_STRIDE)
                                       + gsub * (8 * W_STRIDE);
#pragma unroll
                    for (int t = 0; t < 2; t++) {
                        int n = wn * 16 + t * 8 + grp;
                        unsigned bb0 = wb[tg * W_STRIDE + n];
                        unsigned bb1 = wb[(tg + 4) * W_STRIDE + n];
#pragma unroll
                        for (int mt = 0; mt < 2; mt++)
                            mma_tf32(C[ai][mt][t],
                                     a0[mt], a1[mt], a2[mt], a3[mt], bb0, bb1);
                    }
                }
            }
            if (s < 13) CP_WAIT1(); else CP_WAIT0();   // W(s+1) guaranteed landed
            __syncthreads();
        }
    }

    // ---- fused gate epilogue: exact fp32 h_prev; also emit tf32 bits of h ----
#pragma unroll
    for (int t = 0; t < 2; t++) {
        int col0 = j0 + wn * 16 + t * 8 + 2 * tg;
#pragma unroll
        for (int cc = 0; cc < 2; cc++) {
            int j = col0 + cc;
            float br  = bih[j]       + bhh[j];
            float bz  = bih[256 + j] + bhh[256 + j];
            float bni = bih[512 + j];
            float bnh = bhh[512 + j];
#pragma unroll
            for (int mt = 0; mt < 2; mt++) {
                int mrow = b0 + 32 * wm + 16 * mt + grp;
#pragma unroll
                for (int rr = 0; rr < 2; rr++) {
                    int row = mrow + rr * 8;
                    int ci  = rr * 2 + cc;
                    float vr = C[0][mt][t][ci] + br;
                    float vz = C[1][mt][t][ci] + bz;
                    float n1 = C[2][mt][t][ci] + bni;
                    float n2 = C[3][mt][t][ci] + bnh;
                    float r  = 1.f / (1.f + __expf(-vr));
                    float z  = 1.f / (1.f + __expf(-vz));
                    float n  = tanhf(n1 + r * n2);
                    float hp = hprev[(size_t)row * 256 + j];
                    float hv = (1.f - z) * n + z * hp;
                    hout [(size_t)row * 256 + j] = hv;
                    htout[(size_t)row * 256 + j] = f2tf(hv);
                }
            }
        }
    }
}

// ---- once-per-launch converters ----
__global__ void conv_w(const float* __restrict__ Wih, const float* __restrict__ Whh) {
    const size_t total = 8ULL * WT_PER_UNIT;
    for (size_t i = blockIdx.x * (size_t)blockDim.x + threadIdx.x; i < total;
         i += (size_t)gridDim.x * blockDim.x) {
        int j2 = (int)(i & 63);
        size_t r6 = i >> 6;
        int row = (int)(r6 % 48);
        size_t r7 = r6 / 48;
        int s  = (int)(r7 & 15);
        int jc = (int)((r7 >> 4) & 3);
        int ph = (int)((r7 >> 6) & 1);
        int u  = (int)(r7 >> 7);
        int gate = row >> 4, k = row & 15;
        const float* W = (ph ? Whh : Wih) + (size_t)u * 768 * 256;
        float v = W[((size_t)gate * 256 + jc * 64 + j2) * 256 + s * 16 + k];
        g_wt[i] = f2tf(v);
    }
}
__global__ void conv_x(const float* __restrict__ x) {
    const size_t total = (size_t)B_TOTAL * HDIM;
    for (size_t i = blockIdx.x * (size_t)blockDim.x + threadIdx.x; i < total;
         i += (size_t)gridDim.x * blockDim.x)
        g_xt[i] = f2tf(x[i]);
}
__global__ void init_h(const float* __restrict__ h0, float* __restrict__ hb,
                       unsigned* __restrict__ htb) {
    const size_t total = (size_t)B_TOTAL * HDIM;
    for (size_t i = blockIdx.x * (size_t)blockDim.x + threadIdx.x; i < total;
         i += (size_t)gridDim.x * blockDim.x) {
        float v = h0[i & 255];
        hb[i]  = v;
        htb[i] = f2tf(v);
    }
}

extern "C" void kernel_launch(void* const* d_in, const int* in_sizes, int n_in,
                              void* d_out, int out_size) {
    const float* x   = (const float*)d_in[0];
    const float* Wih = (const float*)d_in[1];
    const float* Whh = (const float*)d_in[2];
    const float* bih = (const float*)d_in[3];
    const float* bhh = (const float*)d_in[4];
    const float* h0  = (const float*)d_in[5];
    float* out = (float*)d_out;

    float *hb; unsigned *htb, *xtb, *wtb;
    cudaGetSymbolAddress((void**)&hb,  g_h);
    cudaGetSymbolAddress((void**)&htb, g_ht);
    cudaGetSymbolAddress((void**)&xtb, g_xt);
    cudaGetSymbolAddress((void**)&wtb, g_wt);
    float*    h0b = hb;                 float*    h1b = hb  + (size_t)B_TOTAL * HDIM;
    unsigned* t0b = htb;                unsigned* t1b = htb + (size_t)B_TOTAL * HDIM;

    cudaFuncSetAttribute(gru_unit, cudaFuncAttributeMaxDynamicSharedMemorySize, SMEM_BYTES);

    conv_w<<<4096, 256>>>(Wih, Whh);
    conv_x<<<2048, 256>>>(x);
    init_h<<<1024, 256>>>(h0, h0b, t0b);

    for (int u = 0; u < 8; u++) {
        const float*    hsrc = (u & 1) ? h1b : h0b;
        const unsigned* tsrc = (u & 1) ? t1b : t0b;
        float*    hdst = (u == 7) ? out : ((u & 1) ? h0b : h1b);
        unsigned* tdst = (u & 1) ? t0b : t1b;    // scratch; unused after u=7
        gru_unit<<<dim3(4, 512), 512, SMEM_BYTES>>>(
            xtb, hsrc, tsrc, hdst, tdst,
            wtb + (size_t)u * WT_PER_UNIT,
            bih + (size_t)u * 768, bhh + (size_t)u * 768);
    }
}

// round 15
// speedup vs baseline: 2.8295x; 1.0975x over previous
#include <cuda_runtime.h>
#include <cstdint>

#define B_TOTAL 65536
#define HDIM    256

// ---------------- scratch (allocation-free) ----------------
__device__ float    g_h [2ULL * B_TOTAL * HDIM];   // exact fp32 hidden (ping-pong)
__device__ unsigned g_ht[2ULL * B_TOTAL * HDIM];   // tf32-bit hidden (ping-pong)
__device__ unsigned g_xt[(size_t)B_TOTAL * HDIM];  // tf32-bit x
// weights pre-converted + pre-tiled: [u][ph][jc4][s8][row96 = gate*32+k][64 j]
#define WT_PER_UNIT (2 * 4 * 8 * 96 * 64)
__device__ unsigned g_wt[8ULL * WT_PER_UNIT];

#define A_STRIDE 260                 // bank map 4*grp+tg, conflict-free (proven)
#define A_WORDS  (128 * A_STRIDE)
#define W_STRIDE 72                  // bank map 8*tg+grp, conflict-free (proven)
#define WSTG     (96 * W_STRIDE)     // 6912 words per k32 ring stage
#define SMEM_WORDS (A_WORDS + 2 * WSTG)
#define SMEM_BYTES (SMEM_WORDS * 4)  // 188416 B (occ 1 by design; RF caps it anyway)

__device__ __forceinline__ unsigned f2tf(float f) {
    unsigned u;
    asm("cvt.rna.tf32.f32 %0, %1;" : "=r"(u) : "f"(f));
    return u;
}
__device__ __forceinline__ uint32_t smem_u32(const void* p) {
    uint32_t a;
    asm("{ .reg .u64 t; cvta.to.shared.u64 t, %1; cvt.u32.u64 %0, t; }"
        : "=r"(a) : "l"(p));
    return a;
}
#define CP16(dst_u32, src_ptr) \
    asm volatile("cp.async.cg.shared.global [%0], [%1], 16;" \
                 :: "r"(dst_u32), "l"(src_ptr))
#define CP_COMMIT()  asm volatile("cp.async.commit_group;" ::: "memory")
#define CP_WAIT0()   asm volatile("cp.async.wait_group 0;" ::: "memory")

__device__ __forceinline__ void mma_tf32(float c[4],
                                         unsigned a0, unsigned a1, unsigned a2, unsigned a3,
                                         unsigned b0, unsigned b1) {
    asm volatile(
        "mma.sync.aligned.m16n8k8.row.col.f32.tf32.tf32.f32 "
        "{%0,%1,%2,%3}, {%4,%5,%6,%7}, {%8,%9}, {%0,%1,%2,%3};\n"
        : "+f"(c[0]), "+f"(c[1]), "+f"(c[2]), "+f"(c[3])
        : "r"(a0), "r"(a1), "r"(a2), "r"(a3), "r"(b0), "r"(b1));
}

// One GRU cell.  Grid (4 j-chunks of 64, 512 batch tiles of 128), 512 threads,
// 16 warps 4(M)x4(N), warp tile 32m x 16n (R8/R14 economics, best measured).
// k32 W ring stages (2-deep, issued 1 ahead): 8 steps/phase instead of 16
// halves the sync-point count that R14's profile showed as the dominant cost.
__global__ void __launch_bounds__(512)
gru_unit(const unsigned* __restrict__ xt, const float* __restrict__ hprev,
         const unsigned* __restrict__ htprev,
         float* __restrict__ hout, unsigned* __restrict__ htout,
         const unsigned* __restrict__ wt,           // this unit's g_wt slice
         const float* __restrict__ bih, const float* __restrict__ bhh) {
    extern __shared__ unsigned smem[];
    const uint32_t sbase = smem_u32(smem);
    unsigned* As = smem;                     // [128][A_STRIDE]
    unsigned* Ws = smem + A_WORDS;           // 2-stage ring [96][W_STRIDE]

    const int tid  = threadIdx.x;
    const int lane = tid & 31;
    const int wid  = tid >> 5;
    const int grp  = lane >> 2;
    const int tg   = lane & 3;
    const int wm   = wid & 3;                // rows 32*wm
    const int wn   = wid >> 2;               // cols 16*wn
    const int jc   = blockIdx.x;
    const int j0   = jc * 64;
    const int b0   = blockIdx.y * 128;

    float C[4][2][2][4];
#pragma unroll
    for (int a = 0; a < 4; a++)
#pragma unroll
        for (int mt = 0; mt < 2; mt++)
#pragma unroll
            for (int t = 0; t < 2; t++)
#pragma unroll
                for (int c = 0; c < 4; c++) C[a][mt][t][c] = 0.f;

    for (int phase = 0; phase < 2; phase++) {
        const unsigned* asrc = (phase ? htprev : xt) + (size_t)b0 * 256;
        const unsigned* wbase = wt + (size_t)(phase * 4 + jc) * 8 * 96 * 64;

        __syncthreads();   // previous phase/epilogue consumers done with smem

        // ---- issue A tile copy: 128 rows x 64 16B-granules ----
#pragma unroll
        for (int i = 0; i < 16; i++) {
            int g = tid + i * 512;           // 0..8191
            int row = g >> 6, q = g & 63;
            CP16(sbase + (uint32_t)(row * A_STRIDE + q * 4) * 4,
                 asrc + (size_t)row * 256 + q * 4);
        }

        auto issueW = [&](int s, int stage) {
#pragma unroll
            for (int i = 0; i < 3; i++) {
                int g = tid + i * 512;       // 1536 granules: 96 rows x 16
                if (g < 1536) {
                    int row = g >> 4, q = g & 15;
                    CP16(sbase + (uint32_t)(A_WORDS + stage * WSTG + row * W_STRIDE + q * 4) * 4,
                         wbase + (size_t)s * 6144 + row * 64 + q * 4);
                }
            }
            CP_COMMIT();
        };

        issueW(0, 0);        // commit covers A + W0 (single group is fine)
        CP_WAIT0();
        __syncthreads();

        const int rowa0 = 32 * wm + grp;
        for (int s = 0; s < 8; s++) {
            if (s < 7) issueW(s + 1, (s + 1) & 1);
            const unsigned* wstage = Ws + (size_t)(s & 1) * WSTG;
#pragma unroll
            for (int gsub = 0; gsub < 4; gsub++) {
                const int kc = s * 32 + gsub * 8 + tg;
                unsigned a0[2], a1[2], a2[2], a3[2];
#pragma unroll
                for (int mt = 0; mt < 2; mt++) {
                    int r0 = rowa0 + 16 * mt;
                    a0[mt] = As[r0       * A_STRIDE + kc];
                    a1[mt] = As[(r0 + 8) * A_STRIDE + kc];
                    a2[mt] = As[r0       * A_STRIDE + kc + 4];
                    a3[mt] = As[(r0 + 8) * A_STRIDE + kc + 4];
                }
#pragma unroll
                for (int gate = 0; gate < 3; gate++) {
                    const int ai = (gate == 2) ? (2 + phase) : gate;
                    const unsigned* wb = wstage + gate * (32 * W_STRIDE)
                                       + gsub * (8 * W_STRIDE);
#pragma unroll
                    for (int t = 0; t < 2; t++) {
                        int n = wn * 16 + t * 8 + grp;
                        unsigned bb0 = wb[tg * W_STRIDE + n];
                        unsigned bb1 = wb[(tg + 4) * W_STRIDE + n];
#pragma unroll
                        for (int mt = 0; mt < 2; mt++)
                            mma_tf32(C[ai][mt][t],
                                     a0[mt], a1[mt], a2[mt], a3[mt], bb0, bb1);
                    }
                }
            }
            CP_WAIT0();      // W(s+1) landed (issued a full step ago)
            __syncthreads(); // all warps done reading stage s&1 before overwrite
        }
    }

    // ---- fused gate epilogue: exact fp32 h_prev; also emit tf32 bits of h ----
#pragma unroll
    for (int t = 0; t < 2; t++) {
        int col0 = j0 + wn * 16 + t * 8 + 2 * tg;
#pragma unroll
        for (int cc = 0; cc < 2; cc++) {
            int j = col0 + cc;
            float br  = bih[j]       + bhh[j];
            float bz  = bih[256 + j] + bhh[256 + j];
            float bni = bih[512 + j];
            float bnh = bhh[512 + j];
#pragma unroll
            for (int mt = 0; mt < 2; mt++) {
                int mrow = b0 + 32 * wm + 16 * mt + grp;
#pragma unroll
                for (int rr = 0; rr < 2; rr++) {
                    int row = mrow + rr * 8;
                    int ci  = rr * 2 + cc;
                    float vr = C[0][mt][t][ci] + br;
                    float vz = C[1][mt][t][ci] + bz;
                    float n1 = C[2][mt][t][ci] + bni;
                    float n2 = C[3][mt][t][ci] + bnh;
                    float r  = 1.f / (1.f + __expf(-vr));
                    float z  = 1.f / (1.f + __expf(-vz));
                    float n  = tanhf(n1 + r * n2);
                    float hp = hprev[(size_t)row * 256 + j];
                    float hv = (1.f - z) * n + z * hp;
                    hout [(size_t)row * 256 + j] = hv;
                    htout[(size_t)row * 256 + j] = f2tf(hv);
                }
            }
        }
    }
}

// ---- once-per-launch converters ----
__global__ void conv_w(const float* __restrict__ Wih, const float* __restrict__ Whh) {
    const size_t total = 8ULL * WT_PER_UNIT;
    for (size_t i = blockIdx.x * (size_t)blockDim.x + threadIdx.x; i < total;
         i += (size_t)gridDim.x * blockDim.x) {
        int j2 = (int)(i & 63);
        size_t r6 = i >> 6;
        int row = (int)(r6 % 96);
        size_t r7 = r6 / 96;
        int s  = (int)(r7 & 7);
        int jc = (int)((r7 >> 3) & 3);
        int ph = (int)((r7 >> 5) & 1);
        int u  = (int)(r7 >> 6);
        int gate = row >> 5, k = row & 31;
        const float* W = (ph ? Whh : Wih) + (size_t)u * 768 * 256;
        float v = W[((size_t)gate * 256 + jc * 64 + j2) * 256 + s * 32 + k];
        g_wt[i] = f2tf(v);
    }
}
__global__ void conv_x(const float* __restrict__ x) {
    const size_t total = (size_t)B_TOTAL * HDIM;
    for (size_t i = blockIdx.x * (size_t)blockDim.x + threadIdx.x; i < total;
         i += (size_t)gridDim.x * blockDim.x)
        g_xt[i] = f2tf(x[i]);
}
__global__ void init_h(const float* __restrict__ h0, float* __restrict__ hb,
                       unsigned* __restrict__ htb) {
    const size_t total = (size_t)B_TOTAL * HDIM;
    for (size_t i = blockIdx.x * (size_t)blockDim.x + threadIdx.x; i < total;
         i += (size_t)gridDim.x * blockDim.x) {
        float v = h0[i & 255];
        hb[i]  = v;
        htb[i] = f2tf(v);
    }
}

extern "C" void kernel_launch(void* const* d_in, const int* in_sizes, int n_in,
                              void* d_out, int out_size) {
    const float* x   = (const float*)d_in[0];
    const float* Wih = (const float*)d_in[1];
    const float* Whh = (const float*)d_in[2];
    const float* bih = (const float*)d_in[3];
    const float* bhh = (const float*)d_in[4];
    const float* h0  = (const float*)d_in[5];
    float* out = (float*)d_out;

    float *hb; unsigned *htb, *xtb, *wtb;
    cudaGetSymbolAddress((void**)&hb,  g_h);
    cudaGetSymbolAddress((void**)&htb, g_ht);
    cudaGetSymbolAddress((void**)&xtb, g_xt);
    cudaGetSymbolAddress((void**)&wtb, g_wt);
    float*    h0b = hb;                 float*    h1b = hb  + (size_t)B_TOTAL * HDIM;
    unsigned* t0b = htb;                unsigned* t1b = htb + (size_t)B_TOTAL * HDIM;

    cudaFuncSetAttribute(gru_unit, cudaFuncAttributeMaxDynamicSharedMemorySize, SMEM_BYTES);

    conv_w<<<4096, 256>>>(Wih, Whh);
    conv_x<<<2048, 256>>>(x);
    init_h<<<1024, 256>>>(h0, h0b, t0b);

    for (int u = 0; u < 8; u++) {
        const float*    hsrc = (u & 1) ? h1b : h0b;
        const unsigned* tsrc = (u & 1) ? t1b : t0b;
        float*    hdst = (u == 7) ? out : ((u & 1) ? h0b : h1b);
        unsigned* tdst = (u & 1) ? t0b : t1b;    // scratch; unused after u=7
        gru_unit<<<dim3(4, 512), 512, SMEM_BYTES>>>(
            xtb, hsrc, tsrc, hdst, tdst,
            wtb + (size_t)u * WT_PER_UNIT,
            bih + (size_t)u * 768, bhh + (size_t)u * 768);
    }
}